// round 16
// baseline (speedup 1.0000x reference)
#include <cuda_runtime.h>
#include <cstdint>

#define Y 256
#define XS 16
#define T 2048
#define NSEG 8
#define CLEN 32
#define NCH 64

#define OFF_ALPHA 0ull
#define OFF_BETA  524288ull
#define OFF_P     1048576ull
#define OFF_GAMMA 1048577ull
#define OFF_XI    1572865ull
#define OFF_PATH  135725057ull

__device__ float g_bx[T * Y];
__device__ float g_At[Y * Y];
__device__ float g_V[Y];            // final Viterbi row only
__device__ int   g_bp[(T - 1) * Y];
__device__ float g_w[T * Y];
__device__ int   g_map[NCH * Y];
__device__ float g_p[1];

// FTZ multiply (matches reference runtime's FTZ+DAZ in the Viterbi underflow window)
__device__ __forceinline__ float mul_ftz(float a, float b) {
    float r;
    asm("mul.rn.ftz.f32 %0,%1,%2;" : "=f"(r) : "f"(a), "f"(b));
    return r;
}

// ---- cluster / mbarrier PTX helpers ----
__device__ __forceinline__ uint32_t s2u(const void* p) {
    uint32_t a;
    asm("{ .reg .u64 t; cvta.to.shared.u64 t, %1; cvt.u32.u64 %0, t; }" : "=r"(a) : "l"(p));
    return a;
}
__device__ __forceinline__ uint32_t ctarank() {
    uint32_t r; asm("mov.u32 %0, %%cluster_ctarank;" : "=r"(r)); return r;
}
__device__ __forceinline__ uint32_t mapa_u32(uint32_t laddr, uint32_t rank) {
    uint32_t r;
    asm("mapa.shared::cluster.u32 %0, %1, %2;" : "=r"(r) : "r"(laddr), "r"(rank));
    return r;
}
// 128B SMEM -> remote SMEM bulk copy; one complete_tx per transfer (async proxy, no cluster fence)
__device__ __forceinline__ void bulk_s2c_128(uint32_t rdst, uint32_t lsrc, uint32_t rmbar) {
    asm volatile("cp.async.bulk.shared::cluster.shared::cta.mbarrier::complete_tx::bytes"
                 " [%0], [%1], 128, [%2];"
                 :: "r"(rdst), "r"(lsrc), "r"(rmbar) : "memory");
}
__device__ __forceinline__ void fence_async_proxy_cta() {
    asm volatile("fence.proxy.async.shared::cta;" ::: "memory");
}
__device__ __forceinline__ void mbar_init(uint32_t addr, uint32_t cnt) {
    asm volatile("mbarrier.init.shared.b64 [%0], %1;" :: "r"(addr), "r"(cnt) : "memory");
}
__device__ __forceinline__ void mbar_expect_tx(uint32_t addr, uint32_t bytes) {
    asm volatile("mbarrier.arrive.expect_tx.shared.b64 _, [%0], %1;"
                 :: "r"(addr), "r"(bytes) : "memory");
}
__device__ __forceinline__ void mbar_wait(uint32_t addr, uint32_t parity) {
    uint32_t done;
    asm volatile("{\n\t.reg .pred p;\n\t"
                 "mbarrier.try_wait.parity.acquire.cta.shared::cta.b64 p, [%1], %2;\n\t"
                 "selp.b32 %0,1,0,p;\n\t}"
                 : "=r"(done) : "r"(addr), "r"(parity) : "memory");
    if (!done) {
        asm volatile("{\n\t.reg .pred P;\n"
                     "WL_%=:\n\t"
                     "mbarrier.try_wait.parity.acquire.cta.shared::cta.b64 P, [%0], %1, 0x989680;\n\t"
                     "@P bra WD_%=;\n\t"
                     "bra WL_%=;\n"
                     "WD_%=:\n\t}"
                     :: "r"(addr), "r"(parity) : "memory");
    }
}

// ---------------- prep: bx, A^T ----------------
__global__ void prep_kernel(const int* __restrict__ x,
                            const float* __restrict__ A,
                            const float* __restrict__ b) {
    int idx = blockIdx.x * blockDim.x + threadIdx.x;
    if (idx < T * Y) {
        int t = idx >> 8, y = idx & (Y - 1);
        g_bx[idx] = b[y * XS + x[t]];
    }
    if (idx < Y * Y) {
        int i = idx >> 8, j = idx & (Y - 1);
        g_At[j * Y + i] = A[idx];
    }
}

#define TXBYTES (NSEG * 128)   // 8 transfers x 128B per barrier per phase

// ---------------- three recurrences: 3 clusters of 8 CTAs, bulk DSMEM exchange ----------------
__global__ __launch_bounds__(256) __cluster_dims__(NSEG, 1, 1)
void recur_kernel(const float* __restrict__ A,
                  const float* __restrict__ pi,
                  float* __restrict__ out) {
    const int role = blockIdx.x / NSEG;
    const int tid = threadIdx.x;
    const int g = tid >> 5;
    const int c = tid & 31;
    const uint32_t rank = ctarank();
    const int colbase = (int)rank * 32;

    __shared__ __align__(16) float vsh[2][Y];
    __shared__ __align__(16) float stg[2][32];   // outgoing 128B staging, double-buffered
    __shared__ float red[256];
    __shared__ int   redi[256];
    __shared__ uint64_t mbar[2];

    // register-resident matrix slice: thread (g,c) owns column colbase+c, rows g*32..g*32+31
    const float* M = (role == 1) ? g_At : A;
    float m[32];
#pragma unroll
    for (int ii = 0; ii < 32; ++ii)
        m[ii] = M[(g * 32 + ii) * Y + colbase + c];

    if (tid == 0) {
        mbar_init(s2u(&mbar[0]), 1);
        mbar_init(s2u(&mbar[1]), 1);
    }
    __syncthreads();
    asm volatile("barrier.cluster.arrive.aligned;" ::: "memory");
    asm volatile("barrier.cluster.wait.aligned;" ::: "memory");

    const uint32_t mb0 = s2u(&mbar[0]);
    const uint32_t mb1 = s2u(&mbar[1]);
    const uint32_t stg0 = s2u(&stg[0][0]);
    const uint32_t stg1 = s2u(&stg[1][0]);

    // loop-invariant remote addresses: my 128B lands at vsh[b][colbase] in every peer
    uint32_t rdst0[NSEG], rdst1[NSEG], rmb0[NSEG], rmb1[NSEG];
    {
        uint32_t l0 = s2u(&vsh[0][colbase]);
        uint32_t l1 = s2u(&vsh[1][colbase]);
#pragma unroll
        for (int r = 0; r < NSEG; ++r) {
            rdst0[r] = mapa_u32(l0, r);
            rdst1[r] = mapa_u32(l1, r);
            rmb0[r]  = mapa_u32(mb0, r);
            rmb1[r]  = mapa_u32(mb1, r);
        }
    }

    int pha0 = 0, pha1 = 0;
    int buf = 0;

    if (role == 0) {
        // ---------------- forward alpha ----------------
        float* alpha = out + OFF_ALPHA;
        float v0 = g_bx[tid] * pi[tid];
        vsh[0][tid] = v0;
        alpha[tid] = v0;
        __syncthreads();
        for (int t = 1; t < T; ++t) {
            int nb = buf ^ 1;
            if (t < T - 1 && tid == 0) mbar_expect_tx(nb ? mb1 : mb0, TXBYTES);
            float bxn = (tid < 32) ? g_bx[t * Y + colbase + tid] : 0.f;
            const float4* v4 = (const float4*)(vsh[buf] + g * 32);
            float a0 = 0.f, a1 = 0.f, a2 = 0.f, a3 = 0.f;
#pragma unroll
            for (int ii = 0; ii < 8; ++ii) {
                float4 vv = v4[ii];
                a0 = fmaf(vv.x, m[ii * 4 + 0], a0);
                a1 = fmaf(vv.y, m[ii * 4 + 1], a1);
                a2 = fmaf(vv.z, m[ii * 4 + 2], a2);
                a3 = fmaf(vv.w, m[ii * 4 + 3], a3);
            }
            red[tid] = (a0 + a1) + (a2 + a3);
            __syncthreads();
            if (tid < 32) {
                float s = red[tid];
#pragma unroll
                for (int q = 1; q < 8; ++q) s += red[q * 32 + tid];
                s *= bxn;
                if (t < T - 1) {
                    stg[nb][tid] = s;
                    __syncwarp();
                    if (tid == 0) {
                        fence_async_proxy_cta();
#pragma unroll
                        for (int r = 0; r < NSEG; ++r)
                            bulk_s2c_128(nb ? rdst1[r] : rdst0[r],
                                         nb ? stg1 : stg0,
                                         nb ? rmb1[r] : rmb0[r]);
                    }
                }
                alpha[(size_t)t * Y + colbase + tid] = s;
            }
            if (t < T - 1) {
                if (nb) { mbar_wait(mb1, pha1); pha1 ^= 1; }
                else    { mbar_wait(mb0, pha0); pha0 ^= 1; }
                buf = nb;
            }
        }
    } else if (role == 1) {
        // ---------------- backward beta (vsh carries premultiplied bx*beta) ----------------
        float* beta = out + OFF_BETA;
        vsh[0][tid] = g_bx[(size_t)(T - 1) * Y + tid];   // bx[T-1] * beta[T-1](=1)
        beta[(size_t)(T - 1) * Y + tid] = 1.f;
        __syncthreads();
        for (int t = T - 2; t >= 0; --t) {
            int nb = buf ^ 1;
            if (t > 0 && tid == 0) mbar_expect_tx(nb ? mb1 : mb0, TXBYTES);
            float bxn = (tid < 32) ? g_bx[t * Y + colbase + tid] : 0.f;
            const float4* v4 = (const float4*)(vsh[buf] + g * 32);
            float a0 = 0.f, a1 = 0.f, a2 = 0.f, a3 = 0.f;
#pragma unroll
            for (int ii = 0; ii < 8; ++ii) {
                float4 vv = v4[ii];
                a0 = fmaf(vv.x, m[ii * 4 + 0], a0);
                a1 = fmaf(vv.y, m[ii * 4 + 1], a1);
                a2 = fmaf(vv.z, m[ii * 4 + 2], a2);
                a3 = fmaf(vv.w, m[ii * 4 + 3], a3);
            }
            red[tid] = (a0 + a1) + (a2 + a3);
            __syncthreads();
            if (tid < 32) {
                float s = red[tid];
#pragma unroll
                for (int q = 1; q < 8; ++q) s += red[q * 32 + tid];
                if (t > 0) {
                    stg[nb][tid] = s * bxn;   // premultiplied for next step
                    __syncwarp();
                    if (tid == 0) {
                        fence_async_proxy_cta();
#pragma unroll
                        for (int r = 0; r < NSEG; ++r)
                            bulk_s2c_128(nb ? rdst1[r] : rdst0[r],
                                         nb ? stg1 : stg0,
                                         nb ? rmb1[r] : rmb0[r]);
                    }
                }
                beta[(size_t)t * Y + colbase + tid] = s;
            }
            if (t > 0) {
                if (nb) { mbar_wait(mb1, pha1); pha1 ^= 1; }
                else    { mbar_wait(mb0, pha0); pha0 ^= 1; }
                buf = nb;
            }
        }
    } else {
        // ---------------- Viterbi ----------------
        float v0 = mul_ftz(g_bx[tid], pi[tid]);
        vsh[0][tid] = v0;
        __syncthreads();
        for (int t = 1; t < T; ++t) {
            int nb = buf ^ 1;
            if (t < T - 1 && tid == 0) mbar_expect_tx(nb ? mb1 : mb0, TXBYTES);
            float bxn = (tid < 32) ? g_bx[t * Y + colbase + tid] : 0.f;
            const float4* v4 = (const float4*)(vsh[buf] + g * 32);
            float best = -1e30f;
            int bi = 0;
#pragma unroll
            for (int ii = 0; ii < 8; ++ii) {
                float4 vv = v4[ii];
                float s0 = mul_ftz(vv.x, m[ii * 4 + 0]);
                float s1 = mul_ftz(vv.y, m[ii * 4 + 1]);
                float s2 = mul_ftz(vv.z, m[ii * 4 + 2]);
                float s3 = mul_ftz(vv.w, m[ii * 4 + 3]);
                if (s0 > best) { best = s0; bi = g * 32 + ii * 4 + 0; }
                if (s1 > best) { best = s1; bi = g * 32 + ii * 4 + 1; }
                if (s2 > best) { best = s2; bi = g * 32 + ii * 4 + 2; }
                if (s3 > best) { best = s3; bi = g * 32 + ii * 4 + 3; }
            }
            red[tid] = best;
            redi[tid] = bi;
            __syncthreads();
            if (tid < 32) {
                float b0 = red[tid];
                int i0 = redi[tid];
#pragma unroll
                for (int q = 1; q < 8; ++q) {       // q ascending: first-max (lowest i) wins
                    float bq = red[q * 32 + tid];
                    if (bq > b0) { b0 = bq; i0 = redi[q * 32 + tid]; }
                }
                float Vn = mul_ftz(bxn, b0);
                if (t < T - 1) {
                    stg[nb][tid] = Vn;
                    __syncwarp();
                    if (tid == 0) {
                        fence_async_proxy_cta();
#pragma unroll
                        for (int r = 0; r < NSEG; ++r)
                            bulk_s2c_128(nb ? rdst1[r] : rdst0[r],
                                         nb ? stg1 : stg0,
                                         nb ? rmb1[r] : rmb0[r]);
                    }
                } else {
                    g_V[colbase + tid] = Vn;   // final row only
                }
                g_bp[(size_t)(t - 1) * Y + colbase + tid] = i0;
            }
            if (t < T - 1) {
                if (nb) { mbar_wait(mb1, pha1); pha1 ^= 1; }
                else    { mbar_wait(mb0, pha0); pha0 ^= 1; }
                buf = nb;
            }
        }
    }
}

// ---------------- p = sum(alpha[T-1]) ----------------
__global__ void p_kernel(float* __restrict__ out) {
    __shared__ float sh[Y];
    int tid = threadIdx.x;
    sh[tid] = out[OFF_ALPHA + (size_t)(T - 1) * Y + tid];
    __syncthreads();
    for (int s = 128; s > 0; s >>= 1) {
        if (tid < s) sh[tid] += sh[tid + s];
        __syncthreads();
    }
    if (tid == 0) { out[OFF_P] = sh[0]; g_p[0] = sh[0]; }
}

// ---------------- gamma + w ----------------
__global__ void gamma_kernel(float* __restrict__ out) {
    int idx = blockIdx.x * blockDim.x + threadIdx.x;
    float p = g_p[0];
    float a = out[OFF_ALPHA + idx];
    float bt = out[OFF_BETA + idx];
    out[OFF_GAMMA + idx] = a * bt / p;
    g_w[idx] = g_bx[idx] * bt;
}

// ---------------- xi: 536MB of stores (DRAM bound) ----------------
__global__ __launch_bounds__(256) void xi_kernel(const float* __restrict__ A,
                                                 float* __restrict__ out) {
    __shared__ float As[32 * Y];
    __shared__ float ash[32];
    const int i0 = blockIdx.y * 32;
    const int j = threadIdx.x;
    for (int idx = j; idx < 32 * Y; idx += 256)
        As[idx] = A[i0 * Y + idx];
    for (int tt = 0; tt < 16; ++tt) {
        int t = blockIdx.x * 16 + tt;
        if (t >= T - 1) break;
        __syncthreads();
        if (j < 32) ash[j] = out[OFF_ALPHA + (size_t)t * Y + i0 + j];
        __syncthreads();
        float wj = g_w[(size_t)(t + 1) * Y + j];
        size_t base = OFF_XI + ((size_t)t * Y + i0) * Y + j;
#pragma unroll 8
        for (int ii = 0; ii < 32; ++ii)
            out[base + (size_t)ii * Y] = ash[ii] * As[ii * Y + j] * wj;
    }
}

// ---------------- Viterbi backtrace: chunk maps ----------------
__global__ __launch_bounds__(256) void vit_maps_kernel() {
    __shared__ int bps[CLEN * Y];
    int ch = blockIdx.x;
    int lo = ch * CLEN;
    int hi = min(lo + CLEN, T - 1);
    int n = hi - lo;
    for (int idx = threadIdx.x; idx < n * Y; idx += 256)
        bps[idx] = g_bp[(size_t)lo * Y + idx];
    __syncthreads();
    int s = threadIdx.x;   // blockDim 256 == Y
    for (int r = n - 1; r >= 0; --r) s = bps[r * Y + s];
    g_map[ch * Y + threadIdx.x] = s;
}

// ---------------- Viterbi tail: argmax, boundary walk, emission ----------------
__global__ __launch_bounds__(256) void vit_tail_kernel(float* __restrict__ out) {
    __shared__ float sv[Y];
    __shared__ int   si[Y];
    __shared__ int   bnd[NCH + 1];
    int tid = threadIdx.x;
    sv[tid] = g_V[tid];
    si[tid] = tid;
    __syncthreads();
    for (int s = 128; s > 0; s >>= 1) {   // first-max (lowest index on ties)
        if (tid < s) {
            float a = sv[tid], b = sv[tid + s];
            if (b > a || (b == a && si[tid + s] < si[tid])) {
                sv[tid] = b; si[tid] = si[tid + s];
            }
        }
        __syncthreads();
    }
    if (tid == 0) {
        int s = si[0];
        bnd[NCH] = s;
        for (int cc = NCH - 1; cc >= 0; --cc) {
            s = g_map[cc * Y + s];
            bnd[cc] = s;
        }
        out[OFF_PATH + (T - 1)] = (float)bnd[NCH];
    }
    __syncthreads();
    if (tid < NCH) {
        int lo = tid * CLEN;
        int hi = min(lo + CLEN, T - 1);
        int s = bnd[tid + 1];
        for (int t = hi - 1; t >= lo; --t) {
            s = g_bp[(size_t)t * Y + s];
            out[OFF_PATH + t] = (float)s;
        }
    }
}

extern "C" void kernel_launch(void* const* d_in, const int* in_sizes, int n_in,
                              void* d_out, int out_size) {
    const int* x = nullptr;
    const float *A = nullptr, *b = nullptr, *pi = nullptr;
    for (int i = 0; i < n_in; ++i) {
        switch (in_sizes[i]) {
            case T:       x  = (const int*)d_in[i];   break;
            case Y * Y:   A  = (const float*)d_in[i]; break;
            case Y * XS:  b  = (const float*)d_in[i]; break;
            case Y:       pi = (const float*)d_in[i]; break;
        }
    }
    float* out = (float*)d_out;

    prep_kernel<<<2048, 256>>>(x, A, b);
    recur_kernel<<<3 * NSEG, 256>>>(A, pi, out);
    p_kernel<<<1, 256>>>(out);
    gamma_kernel<<<T * Y / 256, 256>>>(out);
    xi_kernel<<<dim3(128, 8), 256>>>(A, out);
    vit_maps_kernel<<<NCH, 256>>>();
    vit_tail_kernel<<<1, 256>>>(out);
}

// round 17
// speedup vs baseline: 1.4862x; 1.4862x over previous
#include <cuda_runtime.h>
#include <cstdint>

#define Y 256
#define XS 16
#define T 2048
#define NSEG 8
#define CLEN 32
#define NCH 64

#define OFF_ALPHA 0ull
#define OFF_BETA  524288ull
#define OFF_P     1048576ull
#define OFF_GAMMA 1048577ull
#define OFF_XI    1572865ull
#define OFF_PATH  135725057ull

__device__ float g_bx[T * Y];
__device__ float g_At[Y * Y];
__device__ float g_V[Y];            // final Viterbi row only
__device__ int   g_bp[(T - 1) * Y];
__device__ float g_w[T * Y];
__device__ int   g_map[NCH * Y];
__device__ float g_p[1];

// FTZ multiply (matches reference runtime's FTZ+DAZ in the Viterbi underflow window)
__device__ __forceinline__ float mul_ftz(float a, float b) {
    float r;
    asm("mul.rn.ftz.f32 %0,%1,%2;" : "=f"(r) : "f"(a), "f"(b));
    return r;
}

// ---- cluster / mbarrier PTX helpers ----
__device__ __forceinline__ uint32_t s2u(const void* p) {
    uint32_t a;
    asm("{ .reg .u64 t; cvta.to.shared.u64 t, %1; cvt.u32.u64 %0, t; }" : "=r"(a) : "l"(p));
    return a;
}
__device__ __forceinline__ uint32_t ctarank() {
    uint32_t r; asm("mov.u32 %0, %%cluster_ctarank;" : "=r"(r)); return r;
}
__device__ __forceinline__ uint32_t mapa_u32(uint32_t laddr, uint32_t rank) {
    uint32_t r;
    asm("mapa.shared::cluster.u32 %0, %1, %2;" : "=r"(r) : "r"(laddr), "r"(rank));
    return r;
}
// one-instruction DSMEM store + remote barrier tx-completion (async proxy: no fence)
__device__ __forceinline__ void st_async_b32(uint32_t raddr, uint32_t v, uint32_t rmbar) {
    asm volatile("st.async.shared::cluster.mbarrier::complete_tx::bytes.b32 [%0], %1, [%2];"
                 :: "r"(raddr), "r"(v), "r"(rmbar) : "memory");
}
__device__ __forceinline__ void mbar_init(uint32_t addr, uint32_t cnt) {
    asm volatile("mbarrier.init.shared.b64 [%0], %1;" :: "r"(addr), "r"(cnt) : "memory");
}
__device__ __forceinline__ void mbar_expect_tx(uint32_t addr, uint32_t bytes) {
    asm volatile("mbarrier.arrive.expect_tx.shared.b64 _, [%0], %1;"
                 :: "r"(addr), "r"(bytes) : "memory");
}
__device__ __forceinline__ void mbar_wait(uint32_t addr, uint32_t parity) {
    uint32_t done;
    asm volatile("{\n\t.reg .pred p;\n\t"
                 "mbarrier.try_wait.parity.acquire.cta.shared::cta.b64 p, [%1], %2;\n\t"
                 "selp.b32 %0,1,0,p;\n\t}"
                 : "=r"(done) : "r"(addr), "r"(parity) : "memory");
    if (!done) {
        asm volatile("{\n\t.reg .pred P;\n"
                     "WL_%=:\n\t"
                     "mbarrier.try_wait.parity.acquire.cta.shared::cta.b64 P, [%0], %1, 0x989680;\n\t"
                     "@P bra WD_%=;\n\t"
                     "bra WL_%=;\n"
                     "WD_%=:\n\t}"
                     :: "r"(addr), "r"(parity) : "memory");
    }
}

// ---------------- prep: bx, A^T ----------------
__global__ void prep_kernel(const int* __restrict__ x,
                            const float* __restrict__ A,
                            const float* __restrict__ b) {
    int idx = blockIdx.x * blockDim.x + threadIdx.x;
    if (idx < T * Y) {
        int t = idx >> 8, y = idx & (Y - 1);
        g_bx[idx] = b[y * XS + x[t]];
    }
    if (idx < Y * Y) {
        int i = idx >> 8, j = idx & (Y - 1);
        g_At[j * Y + i] = A[idx];
    }
}

#define TXBYTES (NSEG * 32 * 4)   // 1024 bytes delivered per barrier per phase

// ---------------- three recurrences: 3 clusters of 8 CTAs ----------------
// Warp-autonomous steps: each warp owns 4 output columns end-to-end
// (lane l: column cg + (l&3), rows [32*(l>>2), +32)); shfl reduce; no
// __syncthreads in the 2048-step loop. st.async scalar exchange (R14 transport).
__global__ __launch_bounds__(256) __cluster_dims__(NSEG, 1, 1)
void recur_kernel(const float* __restrict__ A,
                  const float* __restrict__ pi,
                  float* __restrict__ out) {
    const int role = blockIdx.x / NSEG;
    const int tid = threadIdx.x;
    const int w = tid >> 5;
    const int l = tid & 31;
    const uint32_t rank = ctarank();
    const int colbase = (int)rank * 32;
    const int cg = colbase + w * 4;          // this warp's 4 columns
    const int mycol = cg + (l & 3);          // this lane's column
    const int r0 = (l >> 2) * 32;            // this lane's row block

    __shared__ __align__(16) float vsh[2][Y];
    __shared__ uint64_t mbar[2];

    // register-resident matrix slice: 32 rows of my column
    const float* M = (role == 1) ? g_At : A;
    float m[32];
#pragma unroll
    for (int ii = 0; ii < 32; ++ii)
        m[ii] = M[(r0 + ii) * Y + mycol];

    if (tid == 0) {
        mbar_init(s2u(&mbar[0]), 1);
        mbar_init(s2u(&mbar[1]), 1);
    }
    __syncthreads();
    asm volatile("barrier.cluster.arrive.aligned;" ::: "memory");
    asm volatile("barrier.cluster.wait.aligned;" ::: "memory");

    const uint32_t mb0 = s2u(&mbar[0]);
    const uint32_t mb1 = s2u(&mbar[1]);

    // loop-invariant remote addresses for lanes 0-3 (their column's slot in every peer)
    uint32_t rv0[NSEG], rv1[NSEG], rmb0[NSEG], rmb1[NSEG];
    {
        uint32_t l0 = s2u(&vsh[0][mycol]);
        uint32_t l1 = s2u(&vsh[1][mycol]);
#pragma unroll
        for (int r = 0; r < NSEG; ++r) {
            rv0[r]  = mapa_u32(l0, r);
            rv1[r]  = mapa_u32(l1, r);
            rmb0[r] = mapa_u32(mb0, r);
            rmb1[r] = mapa_u32(mb1, r);
        }
    }

    int pha0 = 0, pha1 = 0;
    int buf = 0;

    if (role == 0) {
        // ---------------- forward alpha ----------------
        float* alpha = out + OFF_ALPHA;
        float v0 = g_bx[tid] * pi[tid];
        vsh[0][tid] = v0;
        alpha[tid] = v0;
        __syncthreads();
        for (int t = 1; t < T; ++t) {
            int nb = buf ^ 1;
            if (t < T - 1 && tid == 0) mbar_expect_tx(nb ? mb1 : mb0, TXBYTES);
            float bxn = ((l & 28) == 0) ? g_bx[t * Y + cg + l] : 0.f;  // lanes 0-3
            const float4* v4 = (const float4*)(vsh[buf] + r0);
            float a0 = 0.f, a1 = 0.f, a2 = 0.f, a3 = 0.f;
#pragma unroll
            for (int ii = 0; ii < 8; ++ii) {
                float4 vv = v4[ii];
                a0 = fmaf(vv.x, m[ii * 4 + 0], a0);
                a1 = fmaf(vv.y, m[ii * 4 + 1], a1);
                a2 = fmaf(vv.z, m[ii * 4 + 2], a2);
                a3 = fmaf(vv.w, m[ii * 4 + 3], a3);
            }
            float acc = (a0 + a1) + (a2 + a3);
            acc += __shfl_xor_sync(0xffffffffu, acc, 4);
            acc += __shfl_xor_sync(0xffffffffu, acc, 8);
            acc += __shfl_xor_sync(0xffffffffu, acc, 16);
            if (l < 4) {
                float s = acc * bxn;
                if (t < T - 1) {
                    uint32_t sv = __float_as_uint(s);
#pragma unroll
                    for (int r = 0; r < NSEG; ++r)
                        st_async_b32(nb ? rv1[r] : rv0[r], sv, nb ? rmb1[r] : rmb0[r]);
                }
                alpha[(size_t)t * Y + cg + l] = s;
            }
            if (t < T - 1) {
                if (nb) { mbar_wait(mb1, pha1); pha1 ^= 1; }
                else    { mbar_wait(mb0, pha0); pha0 ^= 1; }
                buf = nb;
            }
        }
    } else if (role == 1) {
        // ---------------- backward beta (vsh carries premultiplied bx*beta) ----------------
        float* beta = out + OFF_BETA;
        vsh[0][tid] = g_bx[(size_t)(T - 1) * Y + tid];   // bx[T-1] * beta[T-1](=1)
        beta[(size_t)(T - 1) * Y + tid] = 1.f;
        __syncthreads();
        for (int t = T - 2; t >= 0; --t) {
            int nb = buf ^ 1;
            if (t > 0 && tid == 0) mbar_expect_tx(nb ? mb1 : mb0, TXBYTES);
            float bxn = ((l & 28) == 0) ? g_bx[t * Y + cg + l] : 0.f;
            const float4* v4 = (const float4*)(vsh[buf] + r0);
            float a0 = 0.f, a1 = 0.f, a2 = 0.f, a3 = 0.f;
#pragma unroll
            for (int ii = 0; ii < 8; ++ii) {
                float4 vv = v4[ii];
                a0 = fmaf(vv.x, m[ii * 4 + 0], a0);
                a1 = fmaf(vv.y, m[ii * 4 + 1], a1);
                a2 = fmaf(vv.z, m[ii * 4 + 2], a2);
                a3 = fmaf(vv.w, m[ii * 4 + 3], a3);
            }
            float acc = (a0 + a1) + (a2 + a3);
            acc += __shfl_xor_sync(0xffffffffu, acc, 4);
            acc += __shfl_xor_sync(0xffffffffu, acc, 8);
            acc += __shfl_xor_sync(0xffffffffu, acc, 16);
            if (l < 4) {
                if (t > 0) {
                    uint32_t sv = __float_as_uint(acc * bxn);   // premultiplied for next step
#pragma unroll
                    for (int r = 0; r < NSEG; ++r)
                        st_async_b32(nb ? rv1[r] : rv0[r], sv, nb ? rmb1[r] : rmb0[r]);
                }
                beta[(size_t)t * Y + cg + l] = acc;
            }
            if (t > 0) {
                if (nb) { mbar_wait(mb1, pha1); pha1 ^= 1; }
                else    { mbar_wait(mb0, pha0); pha0 ^= 1; }
                buf = nb;
            }
        }
    } else {
        // ---------------- Viterbi ----------------
        float v0 = mul_ftz(g_bx[tid], pi[tid]);
        vsh[0][tid] = v0;
        __syncthreads();
        for (int t = 1; t < T; ++t) {
            int nb = buf ^ 1;
            if (t < T - 1 && tid == 0) mbar_expect_tx(nb ? mb1 : mb0, TXBYTES);
            float bxn = ((l & 28) == 0) ? g_bx[t * Y + cg + l] : 0.f;
            const float4* v4 = (const float4*)(vsh[buf] + r0);
            float best = -1e30f;
            int bi = 0;
#pragma unroll
            for (int ii = 0; ii < 8; ++ii) {
                float4 vv = v4[ii];
                float s0 = mul_ftz(vv.x, m[ii * 4 + 0]);
                float s1 = mul_ftz(vv.y, m[ii * 4 + 1]);
                float s2 = mul_ftz(vv.z, m[ii * 4 + 2]);
                float s3 = mul_ftz(vv.w, m[ii * 4 + 3]);
                if (s0 > best) { best = s0; bi = r0 + ii * 4 + 0; }
                if (s1 > best) { best = s1; bi = r0 + ii * 4 + 1; }
                if (s2 > best) { best = s2; bi = r0 + ii * 4 + 2; }
                if (s3 > best) { best = s3; bi = r0 + ii * 4 + 3; }
            }
            // cross-lane max with first-occurrence (lowest row index) tie-break
#pragma unroll
            for (int off = 4; off <= 16; off <<= 1) {
                float ov = __shfl_xor_sync(0xffffffffu, best, off);
                int   oi = __shfl_xor_sync(0xffffffffu, bi, off);
                if (ov > best || (ov == best && oi < bi)) { best = ov; bi = oi; }
            }
            if (l < 4) {
                float Vn = mul_ftz(bxn, best);
                if (t < T - 1) {
                    uint32_t sv = __float_as_uint(Vn);
#pragma unroll
                    for (int r = 0; r < NSEG; ++r)
                        st_async_b32(nb ? rv1[r] : rv0[r], sv, nb ? rmb1[r] : rmb0[r]);
                } else {
                    g_V[cg + l] = Vn;   // final row only
                }
                g_bp[(size_t)(t - 1) * Y + cg + l] = bi;
            }
            if (t < T - 1) {
                if (nb) { mbar_wait(mb1, pha1); pha1 ^= 1; }
                else    { mbar_wait(mb0, pha0); pha0 ^= 1; }
                buf = nb;
            }
        }
    }
}

// ---------------- p = sum(alpha[T-1]) ----------------
__global__ void p_kernel(float* __restrict__ out) {
    __shared__ float sh[Y];
    int tid = threadIdx.x;
    sh[tid] = out[OFF_ALPHA + (size_t)(T - 1) * Y + tid];
    __syncthreads();
    for (int s = 128; s > 0; s >>= 1) {
        if (tid < s) sh[tid] += sh[tid + s];
        __syncthreads();
    }
    if (tid == 0) { out[OFF_P] = sh[0]; g_p[0] = sh[0]; }
}

// ---------------- gamma + w ----------------
__global__ void gamma_kernel(float* __restrict__ out) {
    int idx = blockIdx.x * blockDim.x + threadIdx.x;
    float p = g_p[0];
    float a = out[OFF_ALPHA + idx];
    float bt = out[OFF_BETA + idx];
    out[OFF_GAMMA + idx] = a * bt / p;
    g_w[idx] = g_bx[idx] * bt;
}

// ---------------- xi: 536MB of stores (DRAM bound) ----------------
__global__ __launch_bounds__(256) void xi_kernel(const float* __restrict__ A,
                                                 float* __restrict__ out) {
    __shared__ float As[32 * Y];
    __shared__ float ash[32];
    const int i0 = blockIdx.y * 32;
    const int j = threadIdx.x;
    for (int idx = j; idx < 32 * Y; idx += 256)
        As[idx] = A[i0 * Y + idx];
    for (int tt = 0; tt < 16; ++tt) {
        int t = blockIdx.x * 16 + tt;
        if (t >= T - 1) break;
        __syncthreads();
        if (j < 32) ash[j] = out[OFF_ALPHA + (size_t)t * Y + i0 + j];
        __syncthreads();
        float wj = g_w[(size_t)(t + 1) * Y + j];
        size_t base = OFF_XI + ((size_t)t * Y + i0) * Y + j;
#pragma unroll 8
        for (int ii = 0; ii < 32; ++ii)
            out[base + (size_t)ii * Y] = ash[ii] * As[ii * Y + j] * wj;
    }
}

// ---------------- Viterbi backtrace: chunk maps ----------------
__global__ __launch_bounds__(256) void vit_maps_kernel() {
    __shared__ int bps[CLEN * Y];
    int ch = blockIdx.x;
    int lo = ch * CLEN;
    int hi = min(lo + CLEN, T - 1);
    int n = hi - lo;
    for (int idx = threadIdx.x; idx < n * Y; idx += 256)
        bps[idx] = g_bp[(size_t)lo * Y + idx];
    __syncthreads();
    int s = threadIdx.x;   // blockDim 256 == Y
    for (int r = n - 1; r >= 0; --r) s = bps[r * Y + s];
    g_map[ch * Y + threadIdx.x] = s;
}

// ---------------- Viterbi tail: argmax, boundary walk, emission ----------------
__global__ __launch_bounds__(256) void vit_tail_kernel(float* __restrict__ out) {
    __shared__ float sv[Y];
    __shared__ int   si[Y];
    __shared__ int   bnd[NCH + 1];
    int tid = threadIdx.x;
    sv[tid] = g_V[tid];
    si[tid] = tid;
    __syncthreads();
    for (int s = 128; s > 0; s >>= 1) {   // first-max (lowest index on ties)
        if (tid < s) {
            float a = sv[tid], b = sv[tid + s];
            if (b > a || (b == a && si[tid + s] < si[tid])) {
                sv[tid] = b; si[tid] = si[tid + s];
            }
        }
        __syncthreads();
    }
    if (tid == 0) {
        int s = si[0];
        bnd[NCH] = s;
        for (int cc = NCH - 1; cc >= 0; --cc) {
            s = g_map[cc * Y + s];
            bnd[cc] = s;
        }
        out[OFF_PATH + (T - 1)] = (float)bnd[NCH];
    }
    __syncthreads();
    if (tid < NCH) {
        int lo = tid * CLEN;
        int hi = min(lo + CLEN, T - 1);
        int s = bnd[tid + 1];
        for (int t = hi - 1; t >= lo; --t) {
            s = g_bp[(size_t)t * Y + s];
            out[OFF_PATH + t] = (float)s;
        }
    }
}

extern "C" void kernel_launch(void* const* d_in, const int* in_sizes, int n_in,
                              void* d_out, int out_size) {
    const int* x = nullptr;
    const float *A = nullptr, *b = nullptr, *pi = nullptr;
    for (int i = 0; i < n_in; ++i) {
        switch (in_sizes[i]) {
            case T:       x  = (const int*)d_in[i];   break;
            case Y * Y:   A  = (const float*)d_in[i]; break;
            case Y * XS:  b  = (const float*)d_in[i]; break;
            case Y:       pi = (const float*)d_in[i]; break;
        }
    }
    float* out = (float*)d_out;

    prep_kernel<<<2048, 256>>>(x, A, b);
    recur_kernel<<<3 * NSEG, 256>>>(A, pi, out);
    p_kernel<<<1, 256>>>(out);
    gamma_kernel<<<T * Y / 256, 256>>>(out);
    xi_kernel<<<dim3(128, 8), 256>>>(A, out);
    vit_maps_kernel<<<NCH, 256>>>();
    vit_tail_kernel<<<1, 256>>>(out);
}